// round 4
// baseline (speedup 1.0000x reference)
#include <cuda_runtime.h>
#include <cstddef>

#define B 8
#define L 2048
#define H 8
#define D 64
#define BH 64
#define SK 40
#define U  40
#define HD 512
#define SCALE 0.125f
#define NT 8            // probe key tiles of 256 rows
#define PKT 256
#define QC 256          // probe queries per block
#define KSPLIT 8        // pv key splits
#define KT 256          // scores/pv key tile
#define KPITCH 68       // probe K tile pitch (floats), 16B-aligned rows

// ---- device scratch ----
__device__ float g_M[BH * L];
__device__ int   g_top[BH * U];
__device__ float g_vmean[BH * D];
__device__ unsigned char g_ent[L * SK];
__device__ unsigned char g_off[L * (NT + 1)];
__device__ float g_scores[(size_t)BH * U * L];
__device__ float g_pv[BH * KSPLIT * U * D];

// ------------------------------------------------------------------
// Build per-q inverted sample lists bucketed by 256-row key tile,
// stable in s within each tile (deterministic accumulation order).
// ------------------------------------------------------------------
__global__ void k_build(const int* __restrict__ IS) {
    int q = blockIdx.x * blockDim.x + threadIdx.x;
    if (q >= L) return;
    int idxs[SK];
    int cnt[NT];
    #pragma unroll
    for (int t = 0; t < NT; ++t) cnt[t] = 0;
    #pragma unroll
    for (int s = 0; s < SK; ++s) {
        idxs[s] = IS[q * SK + s];
        cnt[idxs[s] >> 8]++;
    }
    int off[NT + 1];
    off[0] = 0;
    #pragma unroll
    for (int t = 0; t < NT; ++t) off[t + 1] = off[t] + cnt[t];
    #pragma unroll
    for (int t = 0; t <= NT; ++t) g_off[q * (NT + 1) + t] = (unsigned char)off[t];
    int pos[NT];
    #pragma unroll
    for (int t = 0; t < NT; ++t) pos[t] = off[t];
    #pragma unroll
    for (int s = 0; s < SK; ++s) {
        int t = idxs[s] >> 8;
        g_ent[q * SK + pos[t]++] = (unsigned char)(idxs[s] & 255);
    }
}

// ------------------------------------------------------------------
// Probe v4: one query per warp iteration, fully CONVERGENT warps.
// Block stages Q chunk (256x64) + K tile (256 rows) in smem.
// Lane holds float2 of each row; 5 full-mask shfls reduce the dot.
// Lane j accumulates the (max,sum) stats of query j.
// ------------------------------------------------------------------
__global__ __launch_bounds__(256, 1) void k_probe4(const float* __restrict__ Q,
                                                   const float* __restrict__ Kp) {
    extern __shared__ float smem[];
    float* Ksm = smem;                     // PKT * KPITCH
    float* Qsm = smem + PKT * KPITCH;      // QC * 64
    int bh = blockIdx.y, qc = blockIdx.x;
    int b = bh >> 3, h = bh & 7;
    int t = threadIdx.x, w = t >> 5, lane = t & 31;

    // stage Q chunk
    for (int i = t; i < QC * 16; i += 256) {
        int r = i >> 4, c = i & 15;
        *(float4*)&Qsm[r * 64 + c * 4] =
            *(const float4*)&Q[(size_t)(b * L + qc * QC + r) * HD + h * D + c * 4];
    }

    float mxr = -3.4e38f, smr = 0.f;   // lane j owns stats of query (w*32 + j)

    for (int kt = 0; kt < NT; ++kt) {
        __syncthreads();
        const float4* src = (const float4*)(Kp + (size_t)(b * L + kt * PKT) * HD + h * D);
        for (int i = t; i < PKT * 16; i += 256) {
            int r = i >> 4, c = i & 15;
            *(float4*)&Ksm[r * KPITCH + c * 4] = src[(size_t)r * (HD / 4) + c];
        }
        __syncthreads();

        for (int j = 0; j < 32; ++j) {         // query index within warp (uniform)
            int q  = qc * QC + w * 32 + j;
            int o0 = g_off[q * (NT + 1) + kt];
            int o1 = g_off[q * (NT + 1) + kt + 1];
            const unsigned char* ep = g_ent + q * SK;
            float2 qv = *(const float2*)&Qsm[(w * 32 + j) * 64 + 2 * lane];
            float lmx = -3.4e38f, lsm = 0.f;
            for (int e = o0; e < o1; ++e) {    // bound uniform across warp
                int kl = ep[e];                // uniform LDG (L1-cached)
                float2 kv = *(const float2*)&Ksm[kl * KPITCH + 2 * lane];
                float p = qv.x * kv.x;
                p = fmaf(qv.y, kv.y, p);
                p += __shfl_xor_sync(0xffffffffu, p, 1);
                p += __shfl_xor_sync(0xffffffffu, p, 2);
                p += __shfl_xor_sync(0xffffffffu, p, 4);
                p += __shfl_xor_sync(0xffffffffu, p, 8);
                p += __shfl_xor_sync(0xffffffffu, p, 16);
                lmx = fmaxf(lmx, p);
                lsm += p;
            }
            if (lane == j) { mxr = fmaxf(mxr, lmx); smr += lsm; }
        }
    }
    g_M[bh * L + qc * QC + w * 32 + lane] = mxr - smr * (1.f / SK);
}

// ------------------------------------------------------------------
// V mean per (b,h,d)
// ------------------------------------------------------------------
__global__ void k_vmean(const float* __restrict__ V) {
    __shared__ float smem[4 * 64];
    int bh = blockIdx.x; int b = bh >> 3, h = bh & 7;
    int d = threadIdx.x & 63, p = threadIdx.x >> 6;
    float s = 0.f;
    for (int l = p; l < L; l += 4)
        s += V[(size_t)(b * L + l) * HD + h * D + d];
    smem[p * 64 + d] = s;
    __syncthreads();
    if (threadIdx.x < 64) {
        float t = smem[threadIdx.x] + smem[64 + threadIdx.x]
                + smem[128 + threadIdx.x] + smem[192 + threadIdx.x];
        g_vmean[bh * 64 + threadIdx.x] = t * (1.f / L);
    }
}

// ------------------------------------------------------------------
// Top-40 per (b,h): one warp per bh; all shuffles fully converged.
// Packed (monotone f32, ~index) keys preserve jax tie semantics.
// ------------------------------------------------------------------
__global__ void k_topk2() {
    __shared__ unsigned long long key[L];
    int bh = blockIdx.x;
    int lane = threadIdx.x;     // 32 threads
    for (int j = 0; j < 64; ++j) {
        int i = lane * 64 + j;
        unsigned int bits = __float_as_uint(g_M[bh * L + i]);
        bits = (bits & 0x80000000u) ? ~bits : (bits | 0x80000000u);
        key[i] = ((unsigned long long)bits << 32) | (unsigned)(L - 1 - i);
    }
    __syncwarp();
    unsigned long long best = 0ull;
    for (int j = 0; j < 64; ++j) {
        unsigned long long k = key[lane * 64 + j];
        if (k > best) best = k;
    }
    for (int it = 0; it < U; ++it) {
        unsigned long long w = best;
        #pragma unroll
        for (int o = 16; o; o >>= 1) {
            unsigned long long other = __shfl_xor_sync(0xffffffffu, w, o);
            if (other > w) w = other;
        }
        int pos = (L - 1) - (int)(w & 0xffffffffu);
        if (lane == 0) { g_top[bh * U + it] = pos; key[pos] = 0ull; }
        __syncwarp();
        int owner = pos >> 6;
        unsigned long long a  = key[owner * 64 + lane];
        unsigned long long b2 = key[owner * 64 + 32 + lane];
        unsigned long long nb = a > b2 ? a : b2;
        #pragma unroll
        for (int o = 16; o; o >>= 1) {
            unsigned long long other = __shfl_xor_sync(0xffffffffu, nb, o);
            if (other > nb) nb = other;
        }
        if (lane == owner) best = nb;
        __syncwarp();
    }
}

// ------------------------------------------------------------------
// Fill output with broadcast V-mean
// ------------------------------------------------------------------
__global__ void k_fill(float* __restrict__ out) {
    int i4 = blockIdx.x * blockDim.x + threadIdx.x;
    int linear = i4 * 4;
    int d = linear & 63;
    int h = (linear >> 6) & 7;
    int b = linear >> 20;
    float4 v = *(const float4*)&g_vmean[(b * 8 + h) * 64 + d];
    *(float4*)(out + linear) = v;
}

// ------------------------------------------------------------------
// Scores: float4 smem reads, pitch 68 (conflict-free per phase)
// ------------------------------------------------------------------
__global__ void k_scores(const float* __restrict__ Q, const float* __restrict__ Kp) {
    extern __shared__ float smem[];
    float* Ksm = smem;               // KT * 68
    float* Qsm = smem + KT * 68;     // U * 64
    int bh = blockIdx.y, kt = blockIdx.x;
    int b = bh >> 3, h = bh & 7;
    int k0 = kt * KT;
    int t = threadIdx.x;             // 512

    for (int i4 = t; i4 < U * 16; i4 += 512) {
        int u = i4 >> 4, d4 = (i4 & 15) * 4;
        int qidx = g_top[bh * U + u];
        *(float4*)&Qsm[u * 64 + d4] =
            *(const float4*)&Q[(size_t)(b * L + qidx) * HD + h * D + d4];
    }
    for (int i4 = t; i4 < KT * 16; i4 += 512) {
        int k = i4 >> 4, d4 = (i4 & 15) * 4;
        *(float4*)&Ksm[k * 68 + d4] =
            *(const float4*)&Kp[(size_t)(b * L + k0 + k) * HD + h * D + d4];
    }
    __syncthreads();

    int kg = t & 63, ug = t >> 6;
    int u0 = ug * 5;
    float acc[5][4];
    #pragma unroll
    for (int i = 0; i < 5; ++i)
        #pragma unroll
        for (int j = 0; j < 4; ++j) acc[i][j] = 0.f;

    for (int d = 0; d < 64; d += 4) {
        float4 k4[4], q4[5];
        #pragma unroll
        for (int j = 0; j < 4; ++j) k4[j] = *(float4*)&Ksm[(kg + 64 * j) * 68 + d];
        #pragma unroll
        for (int i = 0; i < 5; ++i) q4[i] = *(float4*)&Qsm[(u0 + i) * 64 + d];
        #pragma unroll
        for (int i = 0; i < 5; ++i)
            #pragma unroll
            for (int j = 0; j < 4; ++j) {
                acc[i][j] = fmaf(q4[i].x, k4[j].x, acc[i][j]);
                acc[i][j] = fmaf(q4[i].y, k4[j].y, acc[i][j]);
                acc[i][j] = fmaf(q4[i].z, k4[j].z, acc[i][j]);
                acc[i][j] = fmaf(q4[i].w, k4[j].w, acc[i][j]);
            }
    }
    #pragma unroll
    for (int i = 0; i < 5; ++i)
        #pragma unroll
        for (int j = 0; j < 4; ++j)
            g_scores[(size_t)(bh * U + u0 + i) * L + k0 + kg + 64 * j] = acc[i][j] * SCALE;
}

// ------------------------------------------------------------------
// Row softmax over 2048, in place
// ------------------------------------------------------------------
__global__ void k_softmax() {
    __shared__ float red[8];
    size_t row = blockIdx.x;
    float* p = g_scores + row * L;
    int t = threadIdx.x, lane = t & 31, w = t >> 5;
    float4 v0 = *(float4*)&p[4 * t];
    float4 v1 = *(float4*)&p[4 * (t + 256)];
    float m = fmaxf(fmaxf(fmaxf(v0.x, v0.y), fmaxf(v0.z, v0.w)),
                    fmaxf(fmaxf(v1.x, v1.y), fmaxf(v1.z, v1.w)));
    #pragma unroll
    for (int o = 16; o; o >>= 1) m = fmaxf(m, __shfl_xor_sync(0xffffffffu, m, o));
    if (lane == 0) red[w] = m;
    __syncthreads();
    m = red[0];
    #pragma unroll
    for (int i = 1; i < 8; ++i) m = fmaxf(m, red[i]);
    __syncthreads();

    v0.x = __expf(v0.x - m); v0.y = __expf(v0.y - m);
    v0.z = __expf(v0.z - m); v0.w = __expf(v0.w - m);
    v1.x = __expf(v1.x - m); v1.y = __expf(v1.y - m);
    v1.z = __expf(v1.z - m); v1.w = __expf(v1.w - m);
    float s = v0.x + v0.y + v0.z + v0.w + v1.x + v1.y + v1.z + v1.w;
    #pragma unroll
    for (int o = 16; o; o >>= 1) s += __shfl_xor_sync(0xffffffffu, s, o);
    if (lane == 0) red[w] = s;
    __syncthreads();
    s = red[0];
    #pragma unroll
    for (int i = 1; i < 8; ++i) s += red[i];
    float inv = 1.f / s;
    v0.x *= inv; v0.y *= inv; v0.z *= inv; v0.w *= inv;
    v1.x *= inv; v1.y *= inv; v1.z *= inv; v1.w *= inv;
    *(float4*)&p[4 * t] = v0;
    *(float4*)&p[4 * (t + 256)] = v1;
}

// ------------------------------------------------------------------
// Partial PV per 256-key split
// ------------------------------------------------------------------
__global__ void k_pv(const float* __restrict__ V) {
    extern __shared__ float smem[];
    float* Vsm = smem;               // KT * 64
    float* Asm = smem + KT * 64;     // U * 260
    int bh = blockIdx.y, ks = blockIdx.x;
    int b = bh >> 3, h = bh & 7;
    int k0 = ks * KT;
    int t = threadIdx.x;             // 128

    for (int i4 = t; i4 < U * (KT / 4); i4 += 128) {
        int u = i4 >> 6, k4 = (i4 & 63) * 4;
        *(float4*)&Asm[u * 260 + k4] =
            *(const float4*)&g_scores[(size_t)(bh * U + u) * L + k0 + k4];
    }
    for (int i4 = t; i4 < KT * 16; i4 += 128) {
        int k = i4 >> 4, d4 = (i4 & 15) * 4;
        *(float4*)&Vsm[k * 64 + d4] =
            *(const float4*)&V[(size_t)(b * L + k0 + k) * HD + h * D + d4];
    }
    __syncthreads();

    int ug = t & 7, dg = t >> 3;
    int u0 = ug * 5, d0 = dg * 4;
    float4 acc[5];
    #pragma unroll
    for (int i = 0; i < 5; ++i) acc[i] = make_float4(0.f, 0.f, 0.f, 0.f);

    #pragma unroll 2
    for (int k = 0; k < KT; ++k) {
        float4 v = *(float4*)&Vsm[k * 64 + d0];
        #pragma unroll
        for (int i = 0; i < 5; ++i) {
            float a = Asm[(u0 + i) * 260 + k];
            acc[i].x = fmaf(a, v.x, acc[i].x);
            acc[i].y = fmaf(a, v.y, acc[i].y);
            acc[i].z = fmaf(a, v.z, acc[i].z);
            acc[i].w = fmaf(a, v.w, acc[i].w);
        }
    }
    #pragma unroll
    for (int i = 0; i < 5; ++i)
        *(float4*)&g_pv[(size_t)((bh * KSPLIT + ks) * U + u0 + i) * D + d0] = acc[i];
}

// ------------------------------------------------------------------
// Reduce partials, scatter to output
// ------------------------------------------------------------------
__global__ void k_final(float* __restrict__ out) {
    int i4 = blockIdx.x * blockDim.x + threadIdx.x;
    if (i4 >= BH * U * 16) return;
    int d4 = (i4 & 15) * 4;
    int u  = (i4 >> 4) % U;
    int bh = i4 / (U * 16);
    float4 s = make_float4(0.f, 0.f, 0.f, 0.f);
    #pragma unroll
    for (int ks = 0; ks < KSPLIT; ++ks) {
        float4 p = *(const float4*)&g_pv[(size_t)((bh * KSPLIT + ks) * U + u) * D + d4];
        s.x += p.x; s.y += p.y; s.z += p.z; s.w += p.w;
    }
    int q = g_top[bh * U + u];
    int b = bh >> 3, h = bh & 7;
    *(float4*)&out[(size_t)(b * L + q) * HD + h * D + d4] = s;
}

// ------------------------------------------------------------------
extern "C" void kernel_launch(void* const* d_in, const int* in_sizes, int n_in,
                              void* d_out, int out_size) {
    const float* Q = (const float*)d_in[0];
    const float* K = (const float*)d_in[1];
    const float* V = (const float*)d_in[2];
    const int*  IS = (const int*)d_in[3];
    float* out = (float*)d_out;

    const int smem_probe  = (PKT * KPITCH + QC * 64) * 4;  // 135168
    const int smem_scores = (KT * 68 + U * 64) * 4;        // 79872
    const int smem_pv     = (KT * 64 + U * 260) * 4;       // 107136
    cudaFuncSetAttribute(k_probe4, cudaFuncAttributeMaxDynamicSharedMemorySize, smem_probe);
    cudaFuncSetAttribute(k_scores, cudaFuncAttributeMaxDynamicSharedMemorySize, smem_scores);
    cudaFuncSetAttribute(k_pv,     cudaFuncAttributeMaxDynamicSharedMemorySize, smem_pv);

    k_build  <<<(L + 255) / 256, 256>>>(IS);
    k_vmean  <<<BH, 256>>>(V);
    k_probe4 <<<dim3(L / QC, BH), 256, smem_probe>>>(Q, K);
    k_topk2  <<<BH, 32>>>();
    k_fill   <<<(B * L * HD / 4) / 256, 256>>>(out);
    k_scores <<<dim3(L / KT, BH), 512, smem_scores>>>(Q, K);
    k_softmax<<<BH * U, 256>>>();
    k_pv     <<<dim3(L / KT, BH), 128, smem_pv>>>(V);
    k_final  <<<(BH * U * 16 + 255) / 256, 256>>>(out);
}

// round 5
// speedup vs baseline: 2.4351x; 2.4351x over previous
#include <cuda_runtime.h>
#include <cstddef>

#define B 8
#define L 2048
#define H 8
#define D 64
#define BH 64
#define SK 40
#define U  40
#define HD 512
#define SCALE 0.125f
#define NT 8            // key tiles of 256 rows
#define QC2 256         // probe queries per block
#define KSPLIT 8        // pv key splits
#define KT 256          // scores/pv key tile

// ---- device scratch ----
__device__ float g_M[BH * L];
__device__ int   g_top[BH * U];
__device__ float g_vmean[BH * D];
__device__ unsigned char g_ent[L * SK];
__device__ unsigned char g_off[L * (NT + 1)];
__device__ float g_scores[(size_t)BH * U * L];
__device__ float g_pv[BH * KSPLIT * U * D];

// ------------------------------------------------------------------
// Build per-q inverted sample lists bucketed by 256-row key tile,
// stable in s within each tile (deterministic accumulation order).
// ------------------------------------------------------------------
__global__ void k_build(const int* __restrict__ IS) {
    int q = blockIdx.x * blockDim.x + threadIdx.x;
    if (q >= L) return;
    int idxs[SK];
    int cnt[NT];
    #pragma unroll
    for (int t = 0; t < NT; ++t) cnt[t] = 0;
    #pragma unroll
    for (int s = 0; s < SK; ++s) {
        idxs[s] = IS[q * SK + s];
        cnt[idxs[s] >> 8]++;
    }
    int off[NT + 1];
    off[0] = 0;
    #pragma unroll
    for (int t = 0; t < NT; ++t) off[t + 1] = off[t] + cnt[t];
    #pragma unroll
    for (int t = 0; t <= NT; ++t) g_off[q * (NT + 1) + t] = (unsigned char)off[t];
    int pos[NT];
    #pragma unroll
    for (int t = 0; t < NT; ++t) pos[t] = off[t];
    #pragma unroll
    for (int s = 0; s < SK; ++s) {
        int t = idxs[s] >> 8;
        g_ent[q * SK + pos[t]++] = (unsigned char)(idxs[s] & 255);
    }
}

// ------------------------------------------------------------------
// Probe v6: LDG gather with L1-resident key tiles.
// Warp = 16 query pairs; 16 lanes per query; groups iterate in
// lockstep to max(cA,cB) -> no divergence, full-mask shuffles only.
// ------------------------------------------------------------------
__global__ __launch_bounds__(256, 3) void k_probe6(const float* __restrict__ Q,
                                                   const float* __restrict__ Kp) {
    __shared__ unsigned char ent_sm[QC2 * SK];       // 10240 B
    __shared__ unsigned char off_sm[QC2 * (NT + 1)]; // 2304 B
    int bh = blockIdx.y, qc = blockIdx.x;
    int b = bh >> 3, h = bh & 7;
    int t = threadIdx.x, w = t >> 5, lane = t & 31;
    int qh = lane >> 4, li = lane & 15;
    int qbase0 = qc * QC2;

    {   // stage entry lists + offsets (both 16B/4B aligned)
        const uint4* esrc = (const uint4*)(g_ent + (size_t)qbase0 * SK);
        uint4* edst = (uint4*)ent_sm;
        for (int i = t; i < QC2 * SK / 16; i += 256) edst[i] = esrc[i];
        const unsigned* osrc = (const unsigned*)(g_off + (size_t)qbase0 * (NT + 1));
        unsigned* odst = (unsigned*)off_sm;
        for (int i = t; i < QC2 * (NT + 1) / 4; i += 256) odst[i] = osrc[i];
    }
    __syncthreads();

    const float* Kbase = Kp + (size_t)(b * L) * HD + h * D;
    const float* Qbase = Q  + (size_t)(b * L) * HD + h * D;

    float mxr = -3.4e38f, smr = 0.f;   // lane (qh, li=p) owns stats of pair p's query

    for (int kt = 0; kt < NT; ++kt) {
        #pragma unroll 1
        for (int p = 0; p < 16; ++p) {
            int qloc = w * 32 + 2 * p + qh;                 // group-uniform
            int o0 = off_sm[qloc * (NT + 1) + kt];
            int c  = off_sm[qloc * (NT + 1) + kt + 1] - o0;
            int cmax = c;
            {   // converged full-warp exchange of counts
                int oc = __shfl_xor_sync(0xffffffffu, c, 16);
                if (oc > cmax) cmax = oc;
            }
            float4 qv = *(const float4*)(Qbase + (size_t)(qbase0 + qloc) * HD + 4 * li);
            float lmx = -3.4e38f, lsm = 0.f;
            const unsigned char* ep = ent_sm + qloc * SK;
            int e = 0;
            for (; e + 2 <= cmax; e += 2) {     // 2 independent shuffle chains
                int ea = (e     < c) ? o0 + e     : 0;
                int eb = (e + 1 < c) ? o0 + e + 1 : 0;
                int ka = ep[ea], kb = ep[eb];
                float4 va = __ldg((const float4*)(Kbase + (size_t)((kt << 8) + ka) * HD + 4 * li));
                float4 vb = __ldg((const float4*)(Kbase + (size_t)((kt << 8) + kb) * HD + 4 * li));
                float pa = qv.x * va.x; pa = fmaf(qv.y, va.y, pa);
                pa = fmaf(qv.z, va.z, pa); pa = fmaf(qv.w, va.w, pa);
                float pb = qv.x * vb.x; pb = fmaf(qv.y, vb.y, pb);
                pb = fmaf(qv.z, vb.z, pb); pb = fmaf(qv.w, vb.w, pb);
                #pragma unroll
                for (int o = 1; o <= 8; o <<= 1) {
                    pa += __shfl_xor_sync(0xffffffffu, pa, o);
                    pb += __shfl_xor_sync(0xffffffffu, pb, o);
                }
                if (e < c)     { lmx = fmaxf(lmx, pa); lsm += pa; }
                if (e + 1 < c) { lmx = fmaxf(lmx, pb); lsm += pb; }
            }
            if (e < cmax) {
                int ea = (e < c) ? o0 + e : 0;
                int ka = ep[ea];
                float4 va = __ldg((const float4*)(Kbase + (size_t)((kt << 8) + ka) * HD + 4 * li));
                float pa = qv.x * va.x; pa = fmaf(qv.y, va.y, pa);
                pa = fmaf(qv.z, va.z, pa); pa = fmaf(qv.w, va.w, pa);
                #pragma unroll
                for (int o = 1; o <= 8; o <<= 1)
                    pa += __shfl_xor_sync(0xffffffffu, pa, o);
                if (e < c) { lmx = fmaxf(lmx, pa); lsm += pa; }
            }
            if (li == p) { mxr = fmaxf(mxr, lmx); smr += lsm; }
        }
    }
    // lane (qh, li=p) holds stats for query qbase0 + w*32 + 2p + qh
    int qout = qbase0 + w * 32 + 2 * li + qh;
    g_M[bh * L + qout] = mxr - smr * (1.f / SK);
}

// ------------------------------------------------------------------
// V mean per (b,h,d)
// ------------------------------------------------------------------
__global__ void k_vmean(const float* __restrict__ V) {
    __shared__ float smem[4 * 64];
    int bh = blockIdx.x; int b = bh >> 3, h = bh & 7;
    int d = threadIdx.x & 63, p = threadIdx.x >> 6;
    float s = 0.f;
    for (int l = p; l < L; l += 4)
        s += V[(size_t)(b * L + l) * HD + h * D + d];
    smem[p * 64 + d] = s;
    __syncthreads();
    if (threadIdx.x < 64) {
        float t = smem[threadIdx.x] + smem[64 + threadIdx.x]
                + smem[128 + threadIdx.x] + smem[192 + threadIdx.x];
        g_vmean[bh * 64 + threadIdx.x] = t * (1.f / L);
    }
}

// ------------------------------------------------------------------
// Top-40 per (b,h), two-phase: 8 warps find slice top-40 in regs,
// warp 0 merges 320 candidates. Keys pack (monotone f32, ~index)
// so max-selection matches jax top_k ordering; keys unique.
// ------------------------------------------------------------------
__global__ void k_topk3() {
    __shared__ unsigned long long cand[8 * U];
    int bh = blockIdx.x;
    int t = threadIdx.x, w = t >> 5, lane = t & 31;

    unsigned long long k[8];
    #pragma unroll
    for (int j = 0; j < 8; ++j) {
        int i = w * 256 + j * 32 + lane;
        unsigned bits = __float_as_uint(g_M[bh * L + i]);
        bits = (bits & 0x80000000u) ? ~bits : (bits | 0x80000000u);
        k[j] = ((unsigned long long)bits << 32) | (unsigned)(L - 1 - i);
    }
    for (int it = 0; it < U; ++it) {
        unsigned long long lm = k[0];
        #pragma unroll
        for (int j = 1; j < 8; ++j) if (k[j] > lm) lm = k[j];
        unsigned long long wm = lm;
        #pragma unroll
        for (int o = 16; o; o >>= 1) {
            unsigned long long x = __shfl_xor_sync(0xffffffffu, wm, o);
            if (x > wm) wm = x;
        }
        if (lane == 0) cand[w * U + it] = wm;
        #pragma unroll
        for (int j = 0; j < 8; ++j) if (k[j] == wm) k[j] = 0ull;
    }
    __syncthreads();
    if (w == 0) {
        unsigned long long c[10];
        #pragma unroll
        for (int j = 0; j < 10; ++j) c[j] = cand[j * 32 + lane];
        for (int it = 0; it < U; ++it) {
            unsigned long long lm = c[0];
            #pragma unroll
            for (int j = 1; j < 10; ++j) if (c[j] > lm) lm = c[j];
            unsigned long long wm = lm;
            #pragma unroll
            for (int o = 16; o; o >>= 1) {
                unsigned long long x = __shfl_xor_sync(0xffffffffu, wm, o);
                if (x > wm) wm = x;
            }
            if (lane == 0) g_top[bh * U + it] = (L - 1) - (int)(wm & 0xffffffffu);
            #pragma unroll
            for (int j = 0; j < 10; ++j) if (c[j] == wm) c[j] = 0ull;
        }
    }
}

// ------------------------------------------------------------------
// Fill output with broadcast V-mean
// ------------------------------------------------------------------
__global__ void k_fill(float* __restrict__ out) {
    int i4 = blockIdx.x * blockDim.x + threadIdx.x;
    int linear = i4 * 4;
    int d = linear & 63;
    int h = (linear >> 6) & 7;
    int b = linear >> 20;
    float4 v = *(const float4*)&g_vmean[(b * 8 + h) * 64 + d];
    *(float4*)(out + linear) = v;
}

// ------------------------------------------------------------------
// Scores: float4 smem reads, pitch 68 (conflict-free per phase)
// ------------------------------------------------------------------
__global__ void k_scores(const float* __restrict__ Q, const float* __restrict__ Kp) {
    extern __shared__ float smem[];
    float* Ksm = smem;               // KT * 68
    float* Qsm = smem + KT * 68;     // U * 64
    int bh = blockIdx.y, kt = blockIdx.x;
    int b = bh >> 3, h = bh & 7;
    int k0 = kt * KT;
    int t = threadIdx.x;             // 512

    for (int i4 = t; i4 < U * 16; i4 += 512) {
        int u = i4 >> 4, d4 = (i4 & 15) * 4;
        int qidx = g_top[bh * U + u];
        *(float4*)&Qsm[u * 64 + d4] =
            *(const float4*)&Q[(size_t)(b * L + qidx) * HD + h * D + d4];
    }
    for (int i4 = t; i4 < KT * 16; i4 += 512) {
        int k = i4 >> 4, d4 = (i4 & 15) * 4;
        *(float4*)&Ksm[k * 68 + d4] =
            *(const float4*)&Kp[(size_t)(b * L + k0 + k) * HD + h * D + d4];
    }
    __syncthreads();

    int kg = t & 63, ug = t >> 6;
    int u0 = ug * 5;
    float acc[5][4];
    #pragma unroll
    for (int i = 0; i < 5; ++i)
        #pragma unroll
        for (int j = 0; j < 4; ++j) acc[i][j] = 0.f;

    for (int d = 0; d < 64; d += 4) {
        float4 k4[4], q4[5];
        #pragma unroll
        for (int j = 0; j < 4; ++j) k4[j] = *(float4*)&Ksm[(kg + 64 * j) * 68 + d];
        #pragma unroll
        for (int i = 0; i < 5; ++i) q4[i] = *(float4*)&Qsm[(u0 + i) * 64 + d];
        #pragma unroll
        for (int i = 0; i < 5; ++i)
            #pragma unroll
            for (int j = 0; j < 4; ++j) {
                acc[i][j] = fmaf(q4[i].x, k4[j].x, acc[i][j]);
                acc[i][j] = fmaf(q4[i].y, k4[j].y, acc[i][j]);
                acc[i][j] = fmaf(q4[i].z, k4[j].z, acc[i][j]);
                acc[i][j] = fmaf(q4[i].w, k4[j].w, acc[i][j]);
            }
    }
    #pragma unroll
    for (int i = 0; i < 5; ++i)
        #pragma unroll
        for (int j = 0; j < 4; ++j)
            g_scores[(size_t)(bh * U + u0 + i) * L + k0 + kg + 64 * j] = acc[i][j] * SCALE;
}

// ------------------------------------------------------------------
// Row softmax over 2048, in place
// ------------------------------------------------------------------
__global__ void k_softmax() {
    __shared__ float red[8];
    size_t row = blockIdx.x;
    float* p = g_scores + row * L;
    int t = threadIdx.x, lane = t & 31, w = t >> 5;
    float4 v0 = *(float4*)&p[4 * t];
    float4 v1 = *(float4*)&p[4 * (t + 256)];
    float m = fmaxf(fmaxf(fmaxf(v0.x, v0.y), fmaxf(v0.z, v0.w)),
                    fmaxf(fmaxf(v1.x, v1.y), fmaxf(v1.z, v1.w)));
    #pragma unroll
    for (int o = 16; o; o >>= 1) m = fmaxf(m, __shfl_xor_sync(0xffffffffu, m, o));
    if (lane == 0) red[w] = m;
    __syncthreads();
    m = red[0];
    #pragma unroll
    for (int i = 1; i < 8; ++i) m = fmaxf(m, red[i]);
    __syncthreads();

    v0.x = __expf(v0.x - m); v0.y = __expf(v0.y - m);
    v0.z = __expf(v0.z - m); v0.w = __expf(v0.w - m);
    v1.x = __expf(v1.x - m); v1.y = __expf(v1.y - m);
    v1.z = __expf(v1.z - m); v1.w = __expf(v1.w - m);
    float s = v0.x + v0.y + v0.z + v0.w + v1.x + v1.y + v1.z + v1.w;
    #pragma unroll
    for (int o = 16; o; o >>= 1) s += __shfl_xor_sync(0xffffffffu, s, o);
    if (lane == 0) red[w] = s;
    __syncthreads();
    s = red[0];
    #pragma unroll
    for (int i = 1; i < 8; ++i) s += red[i];
    float inv = 1.f / s;
    v0.x *= inv; v0.y *= inv; v0.z *= inv; v0.w *= inv;
    v1.x *= inv; v1.y *= inv; v1.z *= inv; v1.w *= inv;
    *(float4*)&p[4 * t] = v0;
    *(float4*)&p[4 * (t + 256)] = v1;
}

// ------------------------------------------------------------------
// Partial PV per 256-key split
// ------------------------------------------------------------------
__global__ void k_pv(const float* __restrict__ V) {
    extern __shared__ float smem[];
    float* Vsm = smem;               // KT * 64
    float* Asm = smem + KT * 64;     // U * 260
    int bh = blockIdx.y, ks = blockIdx.x;
    int b = bh >> 3, h = bh & 7;
    int k0 = ks * KT;
    int t = threadIdx.x;             // 128

    for (int i4 = t; i4 < U * (KT / 4); i4 += 128) {
        int u = i4 >> 6, k4 = (i4 & 63) * 4;
        *(float4*)&Asm[u * 260 + k4] =
            *(const float4*)&g_scores[(size_t)(bh * U + u) * L + k0 + k4];
    }
    for (int i4 = t; i4 < KT * 16; i4 += 128) {
        int k = i4 >> 4, d4 = (i4 & 15) * 4;
        *(float4*)&Vsm[k * 64 + d4] =
            *(const float4*)&V[(size_t)(b * L + k0 + k) * HD + h * D + d4];
    }
    __syncthreads();

    int ug = t & 7, dg = t >> 3;
    int u0 = ug * 5, d0 = dg * 4;
    float4 acc[5];
    #pragma unroll
    for (int i = 0; i < 5; ++i) acc[i] = make_float4(0.f, 0.f, 0.f, 0.f);

    #pragma unroll 2
    for (int k = 0; k < KT; ++k) {
        float4 v = *(float4*)&Vsm[k * 64 + d0];
        #pragma unroll
        for (int i = 0; i < 5; ++i) {
            float a = Asm[(u0 + i) * 260 + k];
            acc[i].x = fmaf(a, v.x, acc[i].x);
            acc[i].y = fmaf(a, v.y, acc[i].y);
            acc[i].z = fmaf(a, v.z, acc[i].z);
            acc[i].w = fmaf(a, v.w, acc[i].w);
        }
    }
    #pragma unroll
    for (int i = 0; i < 5; ++i)
        *(float4*)&g_pv[(size_t)((bh * KSPLIT + ks) * U + u0 + i) * D + d0] = acc[i];
}

// ------------------------------------------------------------------
// Reduce partials, scatter to output
// ------------------------------------------------------------------
__global__ void k_final(float* __restrict__ out) {
    int i4 = blockIdx.x * blockDim.x + threadIdx.x;
    if (i4 >= BH * U * 16) return;
    int d4 = (i4 & 15) * 4;
    int u  = (i4 >> 4) % U;
    int bh = i4 / (U * 16);
    float4 s = make_float4(0.f, 0.f, 0.f, 0.f);
    #pragma unroll
    for (int ks = 0; ks < KSPLIT; ++ks) {
        float4 p = *(const float4*)&g_pv[(size_t)((bh * KSPLIT + ks) * U + u) * D + d4];
        s.x += p.x; s.y += p.y; s.z += p.z; s.w += p.w;
    }
    int q = g_top[bh * U + u];
    int b = bh >> 3, h = bh & 7;
    *(float4*)&out[(size_t)(b * L + q) * HD + h * D + d4] = s;
}

// ------------------------------------------------------------------
extern "C" void kernel_launch(void* const* d_in, const int* in_sizes, int n_in,
                              void* d_out, int out_size) {
    const float* Q = (const float*)d_in[0];
    const float* K = (const float*)d_in[1];
    const float* V = (const float*)d_in[2];
    const int*  IS = (const int*)d_in[3];
    float* out = (float*)d_out;

    const int smem_scores = (KT * 68 + U * 64) * 4;        // 79872
    const int smem_pv     = (KT * 64 + U * 260) * 4;       // 107136
    cudaFuncSetAttribute(k_scores, cudaFuncAttributeMaxDynamicSharedMemorySize, smem_scores);
    cudaFuncSetAttribute(k_pv,     cudaFuncAttributeMaxDynamicSharedMemorySize, smem_pv);

    k_build  <<<(L + 255) / 256, 256>>>(IS);
    k_vmean  <<<BH, 256>>>(V);
    k_probe6 <<<dim3(L / QC2, BH), 256>>>(Q, K);
    k_topk3  <<<BH, 256>>>();
    k_fill   <<<(B * L * HD / 4) / 256, 256>>>(out);
    k_scores <<<dim3(L / KT, BH), 512, smem_scores>>>(Q, K);
    k_softmax<<<BH * U, 256>>>();
    k_pv     <<<dim3(L / KT, BH), 128, smem_pv>>>(V);
    k_final  <<<(BH * U * 16 + 255) / 256, 256>>>(out);
}